// round 4
// baseline (speedup 1.0000x reference)
#include <cuda_runtime.h>
#include <cstdint>
#include <cstddef>

// ---------------- problem constants ----------------
#define NU 20000
#define NV 20000
#define NE 320000
#define CU 256
#define CV 256
#define CE 64
#define OU 256
#define OV 256
#define OE 64
#define DU 896   // CU + 2*CV + 2*CE
#define DV 896
#define BN_EPS 1e-5f
#define NEG_BIG (-3.402823466e+38f)

// ---------------- scratch layout (single __device__ arena) ----------------
static constexpr size_t SZ_HU   = (size_t)NU * DU * 4;
static constexpr size_t SZ_HV   = (size_t)NV * DV * 4;
static constexpr size_t SZ_P    = (size_t)NU * 64 * 4;
static constexpr size_t SZ_L    = (size_t)NU * 4;
static constexpr size_t SZ_CNT  = (size_t)NU * 4;
static constexpr size_t SZ_OFF  = 80128;
static constexpr size_t SZ_EID  = (size_t)NE * 4;
static constexpr size_t SZ_RED  = 256;
static constexpr size_t SZ_STAT = 16384;

static constexpr size_t OFF_HU   = 0;
static constexpr size_t OFF_HV   = OFF_HU + SZ_HU;
static constexpr size_t OFF_PU   = OFF_HV + SZ_HV;
static constexpr size_t OFF_PV   = OFF_PU + SZ_P;
static constexpr size_t OFF_LU   = OFF_PV + SZ_P;
static constexpr size_t OFF_LV   = OFF_LU + SZ_L;
static constexpr size_t OFF_WU   = OFF_LV + SZ_L;
static constexpr size_t OFF_WV   = OFF_WU + SZ_L;
static constexpr size_t OFF_CNTU = OFF_WV + SZ_L;
static constexpr size_t OFF_CNTV = OFF_CNTU + SZ_CNT;
static constexpr size_t OFF_OFFU = OFF_CNTV + SZ_CNT;
static constexpr size_t OFF_OFFV = OFF_OFFU + SZ_OFF;
static constexpr size_t OFF_CURU = OFF_OFFV + SZ_OFF;
static constexpr size_t OFF_CURV = OFF_CURU + SZ_CNT;
static constexpr size_t OFF_EIDU = OFF_CURV + SZ_CNT;
static constexpr size_t OFF_EIDV = OFF_EIDU + SZ_EID;
static constexpr size_t OFF_RED  = OFF_EIDV + SZ_EID;
static constexpr size_t OFF_STAT = OFF_RED + SZ_RED;
static constexpr size_t SCRATCH_TOTAL = OFF_STAT + SZ_STAT;

__device__ __align__(256) unsigned char g_scratch[SCRATCH_TOTAL];

__device__ __forceinline__ float*  SF(size_t off) { return (float*)(g_scratch + off); }
__device__ __forceinline__ int*    SI(size_t off) { return (int*)(g_scratch + off); }

// ---------------- init ----------------
__global__ void init_k() {
    int i = blockIdx.x * blockDim.x + threadIdx.x;
    int* cu = SI(OFF_CNTU);
    int* cv = SI(OFF_CNTV);
    float* st = SF(OFF_STAT);
    if (i < NU) { cu[i] = 0; cv[i] = 0; }
    if (i < 1152) st[i] = 0.f;
}

// ---------------- attention logits ----------------
__global__ void logits_k(const float* __restrict__ xus, const float* __restrict__ xvs,
                         const float* __restrict__ attn_u2v, const float* __restrict__ attn_v2u) {
    int w = (blockIdx.x * blockDim.x + threadIdx.x) >> 5;
    int lane = threadIdx.x & 31;
    if (w >= NU + NV) return;
    const float* x; const float* a; float* out; int r;
    if (w < NU) { x = xus; a = attn_u2v; out = SF(OFF_LU); r = w; }
    else        { x = xvs; a = attn_v2u; out = SF(OFF_LV); r = w - NU; }
    float s = 0.f;
    const float* xr = x + (size_t)r * 256;
    #pragma unroll
    for (int k = lane; k < 256; k += 32) s += xr[k] * a[k];
    #pragma unroll
    for (int o = 16; o; o >>= 1) s += __shfl_down_sync(0xffffffffu, s, o);
    if (lane == 0) out[r] = s;
}

__global__ void softmax_reduce_k() {
    const float* l = blockIdx.x ? SF(OFF_LV) : SF(OFF_LU);
    __shared__ float sh[1024];
    int t = threadIdx.x;
    float m = NEG_BIG;
    for (int i = t; i < NU; i += 1024) m = fmaxf(m, l[i]);
    sh[t] = m; __syncthreads();
    for (int s = 512; s; s >>= 1) { if (t < s) sh[t] = fmaxf(sh[t], sh[t + s]); __syncthreads(); }
    float mx = sh[0]; __syncthreads();
    float su = 0.f;
    for (int i = t; i < NU; i += 1024) su += expf(l[i] - mx);
    sh[t] = su; __syncthreads();
    for (int s = 512; s; s >>= 1) { if (t < s) sh[t] += sh[t + s]; __syncthreads(); }
    if (t == 0) { float* red = SF(OFF_RED); red[blockIdx.x * 2] = mx; red[blockIdx.x * 2 + 1] = sh[0]; }
}

__global__ void weights_k() {
    int i = blockIdx.x * blockDim.x + threadIdx.x;
    if (i >= NU) return;
    float* red = SF(OFF_RED);
    SF(OFF_WU)[i] = expf(SF(OFF_LU)[i] - red[0]) / red[1];
    SF(OFF_WV)[i] = expf(SF(OFF_LV)[i] - red[2]) / red[3];
}

// ---------------- CSR build ----------------
__global__ void hist_k(const int* __restrict__ row_v2u, const int* __restrict__ col_u2v) {
    int i = blockIdx.x * blockDim.x + threadIdx.x;
    if (i < NE) atomicAdd(&SI(OFF_CNTU)[row_v2u[i]], 1);
    else if (i < 2 * NE) atomicAdd(&SI(OFF_CNTV)[col_u2v[i - NE]], 1);
}

__global__ void scan_k() {
    const int* cnt = blockIdx.x ? SI(OFF_CNTV) : SI(OFF_CNTU);
    int* off = blockIdx.x ? SI(OFF_OFFV) : SI(OFF_OFFU);
    int* cur = blockIdx.x ? SI(OFF_CURV) : SI(OFF_CURU);
    __shared__ int sh[1024];
    __shared__ int carry;
    int t = threadIdx.x;
    if (t == 0) carry = 0;
    __syncthreads();
    for (int base = 0; base < NU; base += 1024) {
        int i = base + t;
        int v = (i < NU) ? cnt[i] : 0;
        sh[t] = v; __syncthreads();
        for (int s = 1; s < 1024; s <<= 1) {
            int tv = (t >= s) ? sh[t - s] : 0;
            __syncthreads();
            sh[t] += tv;
            __syncthreads();
        }
        int exc = sh[t] - v;
        if (i < NU) { off[i] = carry + exc; cur[i] = carry + exc; }
        __syncthreads();
        if (t == 0) carry += sh[1023];
        __syncthreads();
    }
    if (t == 0) off[NU] = carry;
}

__global__ void scatter_k(const int* __restrict__ row_v2u, const int* __restrict__ col_u2v) {
    int i = blockIdx.x * blockDim.x + threadIdx.x;
    if (i < NE) {
        int p = atomicAdd(&SI(OFF_CURU)[row_v2u[i]], 1);
        SI(OFF_EIDU)[p] = i;
    } else if (i < 2 * NE) {
        int e = i - NE;
        int p = atomicAdd(&SI(OFF_CURV)[col_u2v[e]], 1);
        SI(OFF_EIDV)[p] = e;
    }
}

// ---------------- aggregation ----------------
__global__ __launch_bounds__(256) void agg_k(const int* __restrict__ off, const int* __restrict__ eids,
                      const int* __restrict__ src_of_e,
                      const float* __restrict__ w,
                      const float* __restrict__ xsrc,
                      const float* __restrict__ xe,
                      const float* __restrict__ xtgt,
                      float* __restrict__ h) {
    int u = blockIdx.x;
    int t = threadIdx.x;
    int s = off[u], e = off[u + 1];
    int deg = e - s;
    float sum = 0.f, mx = NEG_BIG, esum = 0.f, emx = NEG_BIG;
    for (int i = s; i < e; i++) {
        int eid = __ldg(&eids[i]);
        int src = __ldg(&src_of_e[eid]);
        float ww = __ldg(&w[src]);
        float v = ww * __ldg(&xsrc[(size_t)src * 256 + t]);
        sum += v;
        mx = fmaxf(mx, v);
        if (t < 64) {
            float ev = __ldg(&xe[(size_t)eid * 64 + t]);
            esum += ev;
            emx = fmaxf(emx, ev);
        }
    }
    float inv = 1.f / (float)(deg > 0 ? deg : 1);
    size_t base = (size_t)u * DU;
    h[base + t]       = xtgt[(size_t)u * 256 + t];
    h[base + 256 + t] = sum * inv;
    h[base + 512 + t] = (deg > 0) ? mx : 0.f;
    if (t < 64) {
        h[base + 768 + t] = esum * inv;
        h[base + 832 + t] = (deg > 0) ? emx : 0.f;
    }
}

// ---------------- 3xTF32 tensor-core GEMM ----------------
// C[M,N] = A[M,K] @ B[K,N], fp32 in/out, tf32 hi/lo split (3 mma passes).
// Block tile 128x64, 8 warps (4x2), warp tile 32x32, BK=16.
// Optional fused epilogue: C += pu[row_e[m]][:] + pv[col_e[m]][:]
__device__ __forceinline__ float tf32_rna(float x) {
    uint32_t u;
    asm("cvt.rna.tf32.f32 %0, %1;" : "=r"(u) : "f"(x));
    return __uint_as_float(u);
}

__device__ __forceinline__ void mma_tf32(float* c,
        uint32_t a0, uint32_t a1, uint32_t a2, uint32_t a3,
        uint32_t b0, uint32_t b1) {
    asm volatile("mma.sync.aligned.m16n8k8.row.col.f32.tf32.tf32.f32 "
        "{%0,%1,%2,%3}, {%4,%5,%6,%7}, {%8,%9}, {%0,%1,%2,%3};"
        : "+f"(c[0]), "+f"(c[1]), "+f"(c[2]), "+f"(c[3])
        : "r"(a0), "r"(a1), "r"(a2), "r"(a3), "r"(b0), "r"(b1));
}

#define SMS 20  // smem row stride (floats): (20m+k)%32 is a lane-perfect permutation

__global__ __launch_bounds__(256, 2) void gemm_tf32(
        const float* __restrict__ A, int lda,
        const float* __restrict__ B, int ldb,
        float* __restrict__ C, int ldc,
        int M, int N, int K,
        const float* __restrict__ pu, const float* __restrict__ pv,
        const int* __restrict__ erow, const int* __restrict__ ecol) {
    __shared__ float As_hi[128][SMS], As_lo[128][SMS];
    __shared__ float Bs_hi[64][SMS],  Bs_lo[64][SMS];

    int tid = threadIdx.x;
    int lane = tid & 31;
    int warp = tid >> 5;
    int wm = warp >> 1;         // 0..3
    int wn = warp & 1;          // 0..1
    int m_block = blockIdx.y * 128;
    int n_block = blockIdx.x * 64;

    float acc[2][4][4];
    #pragma unroll
    for (int i = 0; i < 2; i++)
        #pragma unroll
        for (int j = 0; j < 4; j++)
            #pragma unroll
            for (int l = 0; l < 4; l++) acc[i][j][l] = 0.f;

    // A-load mapping: thread -> (row, k-quarter)
    int a_row = tid >> 1;
    int a_kq  = (tid & 1) * 8;
    // B-load mapping: thread -> (n, k-quad)
    int b_n  = tid & 63;
    int b_kb = (tid >> 6) * 4;

    for (int k0 = 0; k0 < K; k0 += 16) {
        // ---- stage A tile (128 x 16) with tf32 hi/lo split ----
        {
            float4 v0 = make_float4(0.f, 0.f, 0.f, 0.f);
            float4 v1 = v0;
            int gr = m_block + a_row;
            if (gr < M) {
                const float* ap = A + (size_t)gr * lda + k0 + a_kq;
                v0 = *reinterpret_cast<const float4*>(ap);
                v1 = *reinterpret_cast<const float4*>(ap + 4);
            }
            float h0x = tf32_rna(v0.x), h0y = tf32_rna(v0.y), h0z = tf32_rna(v0.z), h0w = tf32_rna(v0.w);
            float h1x = tf32_rna(v1.x), h1y = tf32_rna(v1.y), h1z = tf32_rna(v1.z), h1w = tf32_rna(v1.w);
            *reinterpret_cast<float4*>(&As_hi[a_row][a_kq])     = make_float4(h0x, h0y, h0z, h0w);
            *reinterpret_cast<float4*>(&As_hi[a_row][a_kq + 4]) = make_float4(h1x, h1y, h1z, h1w);
            *reinterpret_cast<float4*>(&As_lo[a_row][a_kq]) = make_float4(
                tf32_rna(v0.x - h0x), tf32_rna(v0.y - h0y), tf32_rna(v0.z - h0z), tf32_rna(v0.w - h0w));
            *reinterpret_cast<float4*>(&As_lo[a_row][a_kq + 4]) = make_float4(
                tf32_rna(v1.x - h1x), tf32_rna(v1.y - h1y), tf32_rna(v1.z - h1z), tf32_rna(v1.w - h1w));
        }
        // ---- stage B tile (16 x 64), transposed to [n][k] ----
        {
            float v[4], h[4], l[4];
            #pragma unroll
            for (int i = 0; i < 4; i++)
                v[i] = B[(size_t)(k0 + b_kb + i) * ldb + n_block + b_n];
            #pragma unroll
            for (int i = 0; i < 4; i++) { h[i] = tf32_rna(v[i]); l[i] = tf32_rna(v[i] - h[i]); }
            *reinterpret_cast<float4*>(&Bs_hi[b_n][b_kb]) = make_float4(h[0], h[1], h[2], h[3]);
            *reinterpret_cast<float4*>(&Bs_lo[b_n][b_kb]) = make_float4(l[0], l[1], l[2], l[3]);
        }
        __syncthreads();

        #pragma unroll
        for (int kk = 0; kk < 16; kk += 8) {
            int kc = kk + (lane & 3);
            uint32_t ah[2][4], al[2][4];
            #pragma unroll
            for (int mt = 0; mt < 2; mt++) {
                int r = wm * 32 + mt * 16 + (lane >> 2);
                ah[mt][0] = __float_as_uint(As_hi[r][kc]);
                ah[mt][1] = __float_as_uint(As_hi[r + 8][kc]);
                ah[mt][2] = __float_as_uint(As_hi[r][kc + 4]);
                ah[mt][3] = __float_as_uint(As_hi[r + 8][kc + 4]);
                al[mt][0] = __float_as_uint(As_lo[r][kc]);
                al[mt][1] = __float_as_uint(As_lo[r + 8][kc]);
                al[mt][2] = __float_as_uint(As_lo[r][kc + 4]);
                al[mt][3] = __float_as_uint(As_lo[r + 8][kc + 4]);
            }
            uint32_t bh[4][2], bl[4][2];
            #pragma unroll
            for (int nt = 0; nt < 4; nt++) {
                int n = wn * 32 + nt * 8 + (lane >> 2);
                bh[nt][0] = __float_as_uint(Bs_hi[n][kc]);
                bh[nt][1] = __float_as_uint(Bs_hi[n][kc + 4]);
                bl[nt][0] = __float_as_uint(Bs_lo[n][kc]);
                bl[nt][1] = __float_as_uint(Bs_lo[n][kc + 4]);
            }
            #pragma unroll
            for (int mt = 0; mt < 2; mt++)
                #pragma unroll
                for (int nt = 0; nt < 4; nt++) {
                    mma_tf32(acc[mt][nt], ah[mt][0], ah[mt][1], ah[mt][2], ah[mt][3], bh[nt][0], bh[nt][1]);
                    mma_tf32(acc[mt][nt], ah[mt][0], ah[mt][1], ah[mt][2], ah[mt][3], bl[nt][0], bl[nt][1]);
                    mma_tf32(acc[mt][nt], al[mt][0], al[mt][1], al[mt][2], al[mt][3], bh[nt][0], bh[nt][1]);
                }
        }
        __syncthreads();
    }

    // ---- epilogue ----
    #pragma unroll
    for (int mt = 0; mt < 2; mt++) {
        int r0 = m_block + wm * 32 + mt * 16 + (lane >> 2);
        #pragma unroll
        for (int half = 0; half < 2; half++) {
            int r = r0 + half * 8;
            if (r >= M) continue;
            float add0[4][2];
            bool fuse = (pu != nullptr);
            int re = 0, ce = 0;
            if (fuse) { re = __ldg(&erow[r]); ce = __ldg(&ecol[r]); }
            #pragma unroll
            for (int nt = 0; nt < 4; nt++) {
                int c = n_block + wn * 32 + nt * 8 + (lane & 3) * 2;
                float x0 = acc[mt][nt][half * 2];
                float x1 = acc[mt][nt][half * 2 + 1];
                if (fuse) {
                    float2 puv = *reinterpret_cast<const float2*>(&pu[(size_t)re * 64 + c]);
                    float2 pvv = *reinterpret_cast<const float2*>(&pv[(size_t)ce * 64 + c]);
                    x0 += puv.x + pvv.x;
                    x1 += puv.y + pvv.y;
                }
                *reinterpret_cast<float2*>(&C[(size_t)r * ldc + c]) = make_float2(x0, x1);
            }
            (void)add0;
        }
    }
}

// ---------------- BN column stats ----------------
__global__ void colstats_k(const float* __restrict__ X, int M, int C,
                           float* __restrict__ sum, float* __restrict__ ssq) {
    size_t tid = blockIdx.x * (size_t)blockDim.x + threadIdx.x;
    size_t stride = (size_t)gridDim.x * blockDim.x;
    int c = (int)(tid % C);
    float s = 0.f, s2 = 0.f;
    size_t total = (size_t)M * C;
    for (size_t i = tid; i < total; i += stride) {
        float v = X[i];
        s += v; s2 += v * v;
    }
    atomicAdd(&sum[c], s);
    atomicAdd(&ssq[c], s2);
}

__global__ void bnfin_k(const float* __restrict__ sum, const float* __restrict__ ssq,
                        const float* __restrict__ g, const float* __restrict__ be,
                        float* __restrict__ scale, float* __restrict__ shift, int M, int C) {
    int c = blockIdx.x * blockDim.x + threadIdx.x;
    if (c >= C) return;
    float mu = sum[c] / (float)M;
    float var = ssq[c] / (float)M - mu * mu;
    float sc = g[c] * rsqrtf(var + BN_EPS);
    scale[c] = sc;
    shift[c] = be[c] - mu * sc;
}

__global__ void bnapply_k(float* __restrict__ X, size_t total, int C,
                          const float* __restrict__ scale, const float* __restrict__ shift) {
    size_t stride = (size_t)gridDim.x * blockDim.x;
    for (size_t i = blockIdx.x * (size_t)blockDim.x + threadIdx.x; i < total; i += stride) {
        int c = (int)(i % C);
        X[i] = X[i] * scale[c] + shift[c];
    }
}

// ---------------- launch ----------------
extern "C" void kernel_launch(void* const* d_in, const int* in_sizes, int n_in,
                              void* d_out, int out_size) {
    const float* xus     = (const float*)d_in[0];
    const float* xut     = (const float*)d_in[1];
    const float* xvs     = (const float*)d_in[2];
    const float* xvt     = (const float*)d_in[3];
    const float* xe_e    = (const float*)d_in[4];
    const float* xe_v2u  = (const float*)d_in[5];
    const float* xe_u2v  = (const float*)d_in[6];
    const int*   row_v2u = (const int*)d_in[7];
    const int*   col_v2u = (const int*)d_in[8];
    const int*   row_u2v = (const int*)d_in[9];
    const int*   col_u2v = (const int*)d_in[10];
    const int*   row_e   = (const int*)d_in[11];
    const int*   col_e   = (const int*)d_in[12];
    const float* attn_v2u = (const float*)d_in[13];
    const float* W_v2u    = (const float*)d_in[14];
    const float* g_v2u    = (const float*)d_in[16];
    const float* be_v2u   = (const float*)d_in[17];
    const float* attn_u2v = (const float*)d_in[18];
    const float* W_u2v    = (const float*)d_in[19];
    const float* g_u2v    = (const float*)d_in[21];
    const float* be_u2v   = (const float*)d_in[22];
    const float* W_e      = (const float*)d_in[23];
    const float* g_e      = (const float*)d_in[25];
    const float* be_e     = (const float*)d_in[26];

    float* out_u = (float*)d_out;
    float* out_v = out_u + (size_t)NU * OU;
    float* out_e = out_v + (size_t)NV * OV;

    unsigned char* base = nullptr;
    cudaGetSymbolAddress((void**)&base, g_scratch);
    float* h_u = (float*)(base + OFF_HU);
    float* h_v = (float*)(base + OFF_HV);
    float* pu  = (float*)(base + OFF_PU);
    float* pv  = (float*)(base + OFF_PV);
    float* wu  = (float*)(base + OFF_WU);
    float* wv  = (float*)(base + OFF_WV);
    int* off_u = (int*)(base + OFF_OFFU);
    int* off_v = (int*)(base + OFF_OFFV);
    int* eid_u = (int*)(base + OFF_EIDU);
    int* eid_v = (int*)(base + OFF_EIDV);
    float* st  = (float*)(base + OFF_STAT);
    float* sum_u = st + 0,    *ssq_u = st + 256;
    float* sum_v = st + 512,  *ssq_v = st + 768;
    float* sum_e = st + 1024, *ssq_e = st + 1088;
    float* scale_u = st + 1152, *shift_u = st + 1408;
    float* scale_v = st + 1664, *shift_v = st + 1920;
    float* scale_e = st + 2176, *shift_e = st + 2240;

    init_k<<<(NU + 255) / 256, 256>>>();
    logits_k<<<(NU + NV) / 8, 256>>>(xus, xvs, attn_u2v, attn_v2u);
    softmax_reduce_k<<<2, 1024>>>();
    weights_k<<<(NU + 255) / 256, 256>>>();
    hist_k<<<(2 * NE + 255) / 256, 256>>>(row_v2u, col_u2v);
    scan_k<<<2, 1024>>>();
    scatter_k<<<(2 * NE + 255) / 256, 256>>>(row_v2u, col_u2v);
    agg_k<<<NU, 256>>>(off_u, eid_u, col_v2u, wv, xvs, xe_v2u, xut, h_u);
    agg_k<<<NV, 256>>>(off_v, eid_v, row_u2v, wu, xus, xe_u2v, xvt, h_v);

    // GEMMs: 3xTF32 tensor-core path (bias skipped: BN-invariant)
    {
        dim3 g1(OU / 64, (NU + 127) / 128);
        gemm_tf32<<<g1, 256>>>(h_u, DU, W_v2u, OU, out_u, OU, NU, OU, DU,
                               nullptr, nullptr, nullptr, nullptr);
        gemm_tf32<<<g1, 256>>>(h_v, DV, W_u2v, OV, out_v, OV, NV, OV, DV,
                               nullptr, nullptr, nullptr, nullptr);
        dim3 g2(1, (NU + 127) / 128);
        gemm_tf32<<<g2, 256>>>(xut, 256, W_e + 64 * 64, 64, pu, 64, NU, 64, 256,
                               nullptr, nullptr, nullptr, nullptr);
        gemm_tf32<<<g2, 256>>>(xvt, 256, W_e + 320 * 64, 64, pv, 64, NV, 64, 256,
                               nullptr, nullptr, nullptr, nullptr);
        // edge GEMM with fused combine: out_e = xe_e@W_e[0:64] + pu[row_e] + pv[col_e]
        dim3 g3(1, NE / 128);
        gemm_tf32<<<g3, 256>>>(xe_e, 64, W_e, 64, out_e, 64, NE, 64, 64,
                               pu, pv, row_e, col_e);
    }

    colstats_k<<<512, 256>>>(out_u, NU, OU, sum_u, ssq_u);
    colstats_k<<<512, 256>>>(out_v, NV, OV, sum_v, ssq_v);
    colstats_k<<<512, 256>>>(out_e, NE, OE, sum_e, ssq_e);
    bnfin_k<<<1, 256>>>(sum_u, ssq_u, g_v2u, be_v2u, scale_u, shift_u, NU, OU);
    bnfin_k<<<1, 256>>>(sum_v, ssq_v, g_u2v, be_u2v, scale_v, shift_v, NV, OV);
    bnfin_k<<<1, 64>>>(sum_e, ssq_e, g_e, be_e, scale_e, shift_e, NE, OE);
    bnapply_k<<<2048, 256>>>(out_u, (size_t)NU * OU, OU, scale_u, shift_u);
    bnapply_k<<<2048, 256>>>(out_v, (size_t)NV * OV, OV, scale_v, shift_v);
    bnapply_k<<<4096, 256>>>(out_e, (size_t)NE * OE, OE, scale_e, shift_e);
}